// round 7
// baseline (speedup 1.0000x reference)
#include <cuda_runtime.h>
#include <cstdint>

#define Bb 8
#define Nn 1024
#define Cc 768
#define Hh 12
#define Dd 64
#define BHh 96
#define Mm 8192
#define SCALEF 0.125f
#define EPSF 1e-8f
#define LNEPS 1e-5f

// ---------------- scratch (device globals) ----------------
__device__ float g_q[2][(size_t)BHh*Nn*Dd];
__device__ float g_k[2][(size_t)BHh*Nn*Dd];
__device__ float g_v[2][(size_t)BHh*Nn*Dd];
__device__ float g_ao[2][(size_t)Mm*Cc];
__device__ float g_pr[2][(size_t)Mm*Cc];
__device__ float g_wt[2][(size_t)3*Cc*Cc];    // W_qkv^T
__device__ float g_wpt[2][(size_t)Cc*Cc];     // W_proj^T
__device__ float g_xr[(size_t)Mm*Cc];         // tf32-rounded x

// ---------------- helpers ----------------
__device__ __forceinline__ uint32_t smem_u32(const void* p) {
    uint32_t a;
    asm("{ .reg .u64 t; cvta.to.shared.u64 t, %1; cvt.u32.u64 %0, t; }" : "=r"(a) : "l"(p));
    return a;
}
__device__ __forceinline__ float rna(float x) {
    uint32_t u;
    asm("cvt.rna.tf32.f32 %0, %1;" : "=r"(u) : "f"(x));
    return __uint_as_float(u);
}
__device__ __forceinline__ void ldsm4(uint32_t& d0, uint32_t& d1, uint32_t& d2, uint32_t& d3, uint32_t a) {
    asm volatile("ldmatrix.sync.aligned.m8n8.x4.shared.b16 {%0,%1,%2,%3}, [%4];"
                 : "=r"(d0), "=r"(d1), "=r"(d2), "=r"(d3) : "r"(a));
}
__device__ __forceinline__ void mma8(float* c, uint32_t a0, uint32_t a1, uint32_t a2, uint32_t a3,
                                     uint32_t b0, uint32_t b1) {
    asm volatile("mma.sync.aligned.m16n8k8.row.col.f32.tf32.tf32.f32 "
                 "{%0,%1,%2,%3},{%4,%5,%6,%7},{%8,%9},{%0,%1,%2,%3};"
                 : "+f"(c[0]), "+f"(c[1]), "+f"(c[2]), "+f"(c[3])
                 : "r"(a0), "r"(a1), "r"(a2), "r"(a3), "r"(b0), "r"(b1));
}
#define CPA16(d, s) asm volatile("cp.async.cg.shared.global [%0], [%1], 16;" :: "r"(d), "l"(s))
#define CPA4(d, s)  asm volatile("cp.async.ca.shared.global [%0], [%1], 4;"  :: "r"(d), "l"(s))
#define CPCOMMIT()  asm volatile("cp.async.commit_group;" ::: "memory")
#define CPWAIT(n)   asm volatile("cp.async.wait_group %0;" :: "n"(n) : "memory")

// =============== shared tf32-mma mainloop: C[128x128] = A * B^T, K=768 ======
__device__ __forceinline__ void gemm_main_768(const float* __restrict__ A,
                                              const float* __restrict__ Bt,
                                              int by, int bx, uint32_t smb,
                                              float acc[2][8][4]) {
    const int tid = threadIdx.x, lane = tid & 31, wid = tid >> 5;
    const int wm = wid >> 1, wn = wid & 1;
    uint32_t dA[4], dB[4];
    const float* sA[4];
    const float* sB[4];
#pragma unroll
    for (int j = 0; j < 4; j++) {
        int e = tid + 256 * j;
        int m = e >> 3, kg = e & 7;
        uint32_t sw = (uint32_t)(m * 128 + ((kg * 16) ^ ((m & 7) << 4)));
        dA[j] = smb + sw;
        dB[j] = smb + 32768u + sw;
        sA[j] = A + (size_t)(by + m) * 768 + kg * 4;
        sB[j] = Bt + (size_t)(bx + m) * 768 + kg * 4;
    }
#pragma unroll
    for (int i = 0; i < 2; i++)
#pragma unroll
        for (int n = 0; n < 8; n++)
#pragma unroll
            for (int c = 0; c < 4; c++) acc[i][n][c] = 0.0f;

#pragma unroll
    for (int j = 0; j < 4; j++) { CPA16(dA[j], sA[j]); CPA16(dB[j], sB[j]); }
    CPCOMMIT();

    const int arow0 = wm * 32 + ((lane >> 3) & 1) * 8 + (lane & 7);
    const int brow0 = wn * 64 + ((lane >> 4) & 1) * 8 + (lane & 7);
    const int axr = (lane & 7) << 4;
    const int agsel = lane >> 4, bgsel = (lane >> 3) & 1;

    for (int it = 0; it < 24; ++it) {
        if (it + 1 < 24) {
            int kc = (it + 1) * 32;
            uint32_t ob = ((it + 1) & 1) ? 16384u : 0u;
#pragma unroll
            for (int j = 0; j < 4; j++) { CPA16(dA[j] + ob, sA[j] + kc); CPA16(dB[j] + ob, sB[j] + kc); }
        }
        CPCOMMIT();
        CPWAIT(1);
        __syncthreads();
        uint32_t Ab = smb + ((it & 1) ? 16384u : 0u);
        uint32_t Bbf = smb + 32768u + ((it & 1) ? 16384u : 0u);
#pragma unroll
        for (int ks = 0; ks < 4; ks++) {
            uint32_t a[2][4];
#pragma unroll
            for (int mt = 0; mt < 2; mt++) {
                int r = arow0 + mt * 16;
                ldsm4(a[mt][0], a[mt][1], a[mt][2], a[mt][3],
                      Ab + r * 128 + (((ks * 2 + agsel) * 16) ^ axr));
            }
#pragma unroll
            for (int j2 = 0; j2 < 4; j2++) {
                int r = brow0 + j2 * 16;
                uint32_t b0, b1, b2, b3;
                ldsm4(b0, b1, b2, b3, Bbf + r * 128 + (((ks * 2 + bgsel) * 16) ^ axr));
#pragma unroll
                for (int mt = 0; mt < 2; mt++) {
                    mma8(acc[mt][2 * j2],     a[mt][0], a[mt][1], a[mt][2], a[mt][3], b0, b1);
                    mma8(acc[mt][2 * j2 + 1], a[mt][0], a[mt][1], a[mt][2], a[mt][3], b2, b3);
                }
            }
        }
        __syncthreads();
    }
}

// ================= 1) qkv GEMM + scatter epilogue ===========================
__global__ __launch_bounds__(256, 2) void k_qkv_mma(const float* __restrict__ X,
                                                    const float* __restrict__ Wt, int br) {
    extern __shared__ char smch[];
    uint32_t smb = smem_u32(smch);
    int bx = blockIdx.x * 128, by = blockIdx.y * 128;
    float acc[2][8][4];
    gemm_main_768(X, Wt, by, bx, smb, acc);

    int lane = threadIdx.x & 31, wid = threadIdx.x >> 5;
    int wm = wid >> 1, wn = wid & 1, g = lane >> 2, tig = lane & 3;
    int colbase = bx + wn * 64;
    int seg = colbase >> 6;
    int three = seg / 12, hseg = seg - three * 12;
    float* base3 = (three == 0) ? g_q[br] : ((three == 1) ? g_k[br] : g_v[br]);
#pragma unroll
    for (int mt = 0; mt < 2; mt++) {
        int m1 = by + wm * 32 + mt * 16 + g;
        int b1 = m1 >> 10, n1 = m1 & 1023;
        float* p1 = base3 + (((size_t)(b1 * 12 + hseg)) * 1024 + n1) * 64 + 2 * tig;
        float* p2 = p1 + (size_t)8 * 64;
#pragma unroll
        for (int nt = 0; nt < 8; nt++) {
            *(float2*)(p1 + nt * 8) = make_float2(rna(acc[mt][nt][0]), rna(acc[mt][nt][1]));
            *(float2*)(p2 + nt * 8) = make_float2(rna(acc[mt][nt][2]), rna(acc[mt][nt][3]));
        }
    }
}

// ================= 2) proj GEMM + bias ======================================
__global__ __launch_bounds__(256, 2) void k_proj_mma(int br, const float* __restrict__ Wt,
                                                     const float* __restrict__ bias) {
    extern __shared__ char smch[];
    uint32_t smb = smem_u32(smch);
    int bx = blockIdx.x * 128, by = blockIdx.y * 128;
    float acc[2][8][4];
    gemm_main_768(g_ao[br], Wt, by, bx, smb, acc);

    int lane = threadIdx.x & 31, wid = threadIdx.x >> 5;
    int wm = wid >> 1, wn = wid & 1, g = lane >> 2, tig = lane & 3;
    int colbase = bx + wn * 64;
#pragma unroll
    for (int mt = 0; mt < 2; mt++) {
        int m1 = by + wm * 32 + mt * 16 + g;
        float* p1 = g_pr[br] + (size_t)m1 * 768 + colbase + 2 * tig;
        float* p2 = p1 + (size_t)8 * 768;
#pragma unroll
        for (int nt = 0; nt < 8; nt++) {
            float2 bv = *(const float2*)(bias + colbase + nt * 8 + 2 * tig);
            *(float2*)(p1 + nt * 8) = make_float2(acc[mt][nt][0] + bv.x, acc[mt][nt][1] + bv.y);
            *(float2*)(p2 + nt * 8) = make_float2(acc[mt][nt][2] + bv.x, acc[mt][nt][3] + bv.y);
        }
    }
}

// ====== 3) FUSED attention, 512 threads / 16 warps ==========================
// smem: Q0 @0 (32K) Q1 @32768 | K0 @65536 (16K) K1 @81920 |
//       V0 @98304 (17408, 64 d-rows x 272B) V1 @115712 | E @133120 (32K)
#define FSQ1 32768u
#define FSK0 65536u
#define FSK1 81920u
#define FSV0 98304u
#define FSV1 115712u
#define FSE  133120u
#define F_SMEM 165888

__device__ __forceinline__ void issue_kv(uint32_t smb, uint32_t sko, uint32_t svo,
                                         const float* __restrict__ Kg,
                                         const float* __restrict__ Vg,
                                         int j0, int tid) {
#pragma unroll
    for (int jj = 0; jj < 2; jj++) {
        int e = tid + 512 * jj;
        int n = e >> 4, kg = e & 15;
        uint32_t dst = smb + sko + n * 256 + ((kg * 16) ^ ((n & 7) << 4));
        CPA16(dst, Kg + (size_t)(j0 + n) * 64 + kg * 4);
    }
    int vn = tid & 63, vkq = tid >> 6;   // vkq 0..7
    uint32_t vb = smb + svo + vn * 272;
    const float* vs = Vg + (size_t)j0 * 64 + vn;
#pragma unroll
    for (int jj = 0; jj < 8; jj++) {
        int k = vkq * 8 + jj;
        CPA4(vb + k * 4, vs + (size_t)k * 64);
    }
    CPCOMMIT();
}

__global__ __launch_bounds__(512, 1) void k_attn(const float* __restrict__ temp_ptr) {
    extern __shared__ char smch[];
    uint32_t smb = smem_u32(smch);
    const int head = blockIdx.y, i0 = blockIdx.x * 128;
    const int tid = threadIdx.x, lane = tid & 31, wid = tid >> 5;
    const int wm = wid >> 1, wn = wid & 1;
    const float* Qg0 = g_q[0] + (size_t)head * 65536;
    const float* Qg1 = g_q[1] + (size_t)head * 65536;
    const float* Kg0 = g_k[0] + (size_t)head * 65536;
    const float* Kg1 = g_k[1] + (size_t)head * 65536;
    const float* Vg0 = g_v[0] + (size_t)head * 65536;
    const float* Vg1 = g_v[1] + (size_t)head * 65536;

    // persistent Q (both branches), group 1
#pragma unroll
    for (int j = 0; j < 8; j++) {
        int e = tid + 512 * j;
        int br = e >> 11, r = e & 2047;
        int n = r >> 4, kg = r & 15;
        uint32_t dst = smb + (uint32_t)(br ? FSQ1 : 0u) + n * 256 + ((kg * 16) ^ ((n & 7) << 4));
        const float* src = (br ? Qg1 : Qg0) + (size_t)(i0 + n) * 64 + kg * 4;
        CPA16(dst, src);
    }
    CPCOMMIT();
    issue_kv(smb, FSK0, FSV0, Kg0, Vg0, 0, tid);   // group 2
    issue_kv(smb, FSK1, FSV1, Kg1, Vg1, 0, tid);   // group 3

    // fragment indices: warp = (wm rows-16-group, wn 32-col half)
    const int arow = wm * 16 + ((lane >> 3) & 1) * 8 + (lane & 7);
    const int brow0 = wn * 32 + ((lane >> 4) & 1) * 8 + (lane & 7);
    const int axr = (lane & 7) << 4;
    const int agsel = lane >> 4, bgsel = (lane >> 3) & 1;
    const int g = lane >> 2, tig = lane & 3;
    const int r1 = wm * 16 + g, r2 = r1 + 8;
    const int sw1 = (r1 & 7) << 4, sw2 = (r2 & 7) << 4;
    char* e1base = smch + FSE + r1 * 256 + wn * 128 + (tig & 1) * 8;
    char* e2base = smch + FSE + r2 * 256 + wn * 128 + (tig & 1) * 8;
    const int tg2 = tig >> 1;

    float O0[4][4], O1[4][4];
#pragma unroll
    for (int n = 0; n < 4; n++)
#pragma unroll
        for (int c = 0; c < 4; c++) { O0[n][c] = 0.f; O1[n][c] = 0.f; }
    float z0[2] = {0.f, 0.f}, z1[2] = {0.f, 0.f}, dt[2] = {0.f, 0.f};

    for (int jt = 0; jt < 16; jt++) {
        // ---------- branch 0 ----------
        CPWAIT(1);
        __syncthreads();
        float acc[4][4];
#pragma unroll
        for (int n = 0; n < 4; n++)
#pragma unroll
            for (int c = 0; c < 4; c++) acc[n][c] = 0.f;
#pragma unroll
        for (int ks = 0; ks < 8; ks++) {
            uint32_t a0, a1, a2, a3;
            ldsm4(a0, a1, a2, a3, smb + arow * 256 + (((ks * 2 + agsel) * 16) ^ axr));
#pragma unroll
            for (int j2 = 0; j2 < 2; j2++) {
                uint32_t boff = FSK0 + (brow0 + j2 * 16) * 256 + (((ks * 2 + bgsel) * 16) ^ axr);
                uint32_t b0, b1, b2, b3;
                ldsm4(b0, b1, b2, b3, smb + boff);
                mma8(acc[2 * j2],     a0, a1, a2, a3, b0, b1);
                mma8(acc[2 * j2 + 1], a0, a1, a2, a3, b2, b3);
            }
        }
#pragma unroll
        for (int nt = 0; nt < 4; nt++) {
            float ea = rna(__expf(fminf(fmaxf(acc[nt][0] * SCALEF, -20.f), 20.f) - 20.f));
            float eb = rna(__expf(fminf(fmaxf(acc[nt][1] * SCALEF, -20.f), 20.f) - 20.f));
            float ec = rna(__expf(fminf(fmaxf(acc[nt][2] * SCALEF, -20.f), 20.f) - 20.f));
            float ed = rna(__expf(fminf(fmaxf(acc[nt][3] * SCALEF, -20.f), 20.f) - 20.f));
            z0[0] += ea + eb; z0[1] += ec + ed;
            int off = ((2 * nt + tg2) * 16);
            *(float2*)(e1base + (off ^ sw1)) = make_float2(ea, eb);
            *(float2*)(e2base + (off ^ sw2)) = make_float2(ec, ed);
        }
        __syncthreads();
#pragma unroll
        for (int ks = 0; ks < 8; ks++) {
            uint32_t a0, a1, a2, a3;
            ldsm4(a0, a1, a2, a3, smb + FSE + arow * 256 + (((ks * 2 + agsel) * 16) ^ axr));
#pragma unroll
            for (int j2 = 0; j2 < 2; j2++) {
                uint32_t b0, b1, b2, b3;
                ldsm4(b0, b1, b2, b3, smb + FSV0 + (brow0 + j2 * 16) * 272 + (ks * 2 + bgsel) * 16);
                mma8(O0[2 * j2],     a0, a1, a2, a3, b0, b1);
                mma8(O0[2 * j2 + 1], a0, a1, a2, a3, b2, b3);
            }
        }
        __syncthreads();
        if (jt + 1 < 16) issue_kv(smb, FSK0, FSV0, Kg0, Vg0, (jt + 1) * 64, tid);
        else CPCOMMIT();
        CPWAIT(1);
        __syncthreads();
        // ---------- branch 1 ----------
#pragma unroll
        for (int n = 0; n < 4; n++)
#pragma unroll
            for (int c = 0; c < 4; c++) acc[n][c] = 0.f;
#pragma unroll
        for (int ks = 0; ks < 8; ks++) {
            uint32_t a0, a1, a2, a3;
            ldsm4(a0, a1, a2, a3, smb + FSQ1 + arow * 256 + (((ks * 2 + agsel) * 16) ^ axr));
#pragma unroll
            for (int j2 = 0; j2 < 2; j2++) {
                uint32_t boff = FSK1 + (brow0 + j2 * 16) * 256 + (((ks * 2 + bgsel) * 16) ^ axr);
                uint32_t b0, b1, b2, b3;
                ldsm4(b0, b1, b2, b3, smb + boff);
                mma8(acc[2 * j2],     a0, a1, a2, a3, b0, b1);
                mma8(acc[2 * j2 + 1], a0, a1, a2, a3, b2, b3);
            }
        }
#pragma unroll
        for (int nt = 0; nt < 4; nt++) {
            float ea = rna(__expf(fminf(fmaxf(acc[nt][0] * SCALEF, -20.f), 20.f) - 20.f));
            float eb = rna(__expf(fminf(fmaxf(acc[nt][1] * SCALEF, -20.f), 20.f) - 20.f));
            float ec = rna(__expf(fminf(fmaxf(acc[nt][2] * SCALEF, -20.f), 20.f) - 20.f));
            float ed = rna(__expf(fminf(fmaxf(acc[nt][3] * SCALEF, -20.f), 20.f) - 20.f));
            z1[0] += ea + eb; z1[1] += ec + ed;
            int off = ((2 * nt + tg2) * 16);
            float2 p1 = *(float2*)(e1base + (off ^ sw1));
            float2 p2 = *(float2*)(e2base + (off ^ sw2));
            dt[0] += p1.x * ea + p1.y * eb;
            dt[1] += p2.x * ec + p2.y * ed;
            *(float2*)(e1base + (off ^ sw1)) = make_float2(ea, eb);
            *(float2*)(e2base + (off ^ sw2)) = make_float2(ec, ed);
        }
        __syncthreads();
#pragma unroll
        for (int ks = 0; ks < 8; ks++) {
            uint32_t a0, a1, a2, a3;
            ldsm4(a0, a1, a2, a3, smb + FSE + arow * 256 + (((ks * 2 + agsel) * 16) ^ axr));
#pragma unroll
            for (int j2 = 0; j2 < 2; j2++) {
                uint32_t b0, b1, b2, b3;
                ldsm4(b0, b1, b2, b3, smb + FSV1 + (brow0 + j2 * 16) * 272 + (ks * 2 + bgsel) * 16);
                mma8(O1[2 * j2],     a0, a1, a2, a3, b0, b1);
                mma8(O1[2 * j2 + 1], a0, a1, a2, a3, b2, b3);
            }
        }
        __syncthreads();
        if (jt + 1 < 16) issue_kv(smb, FSK1, FSV1, Kg1, Vg1, (jt + 1) * 64, tid);
        else CPCOMMIT();
    }

    // ---------- epilogue: combine z/dt across wn pairs, constants, scatter ---
    // reduce within quad first
#pragma unroll
    for (int h = 0; h < 2; h++) {
        z0[h] += __shfl_xor_sync(0xffffffffu, z0[h], 1); z0[h] += __shfl_xor_sync(0xffffffffu, z0[h], 2);
        z1[h] += __shfl_xor_sync(0xffffffffu, z1[h], 1); z1[h] += __shfl_xor_sync(0xffffffffu, z1[h], 2);
        dt[h] += __shfl_xor_sync(0xffffffffu, dt[h], 1); dt[h] += __shfl_xor_sync(0xffffffffu, dt[h], 2);
    }
    float* zz0 = (float*)(smch + FSE);
    float* zz1 = zz0 + 128;
    float* dd  = zz0 + 256;
    if (wn == 0 && tig == 0) {
        zz0[r1] = z0[0]; zz0[r2] = z0[1];
        zz1[r1] = z1[0]; zz1[r2] = z1[1];
        dd[r1]  = dt[0]; dd[r2]  = dt[1];
    }
    __syncthreads();
    if (wn == 1 && tig == 0) {
        zz0[r1] += z0[0]; zz0[r2] += z0[1];
        zz1[r1] += z1[0]; zz1[r2] += z1[1];
        dd[r1]  += dt[0]; dd[r2]  += dt[1];
    }
    __syncthreads();
    float temp = fminf(fmaxf(*temp_ptr, 0.1f), 5.0f);
    float c0r[2], c1r[2];
#pragma unroll
    for (int h = 0; h < 2; h++) {
        int rr = h ? r2 : r1;
        float a = zz0[rr], b = zz1[rr], d = dd[rr];
        float overlap = d / (a * b) + 2.0f * EPSF + 1024.0f * EPSF * EPSF;
        float mask = 1.0f / (1.0f + __expf(overlap * temp));
        float f = mask / (mask + EPSF);
        c0r[h] = f / a;
        c1r[h] = f / b;
    }
    int bidx = head / 12, hh = head - bidx * 12;
    int n1 = i0 + r1;
    int cb = hh * 64 + wn * 32 + 2 * tig;
    float* p1a = g_ao[0] + ((size_t)(bidx * 1024 + n1)) * 768 + cb;
    float* p2a = g_ao[0] + ((size_t)(bidx * 1024 + n1 + 8)) * 768 + cb;
    float* p1b = g_ao[1] + ((size_t)(bidx * 1024 + n1)) * 768 + cb;
    float* p2b = g_ao[1] + ((size_t)(bidx * 1024 + n1 + 8)) * 768 + cb;
#pragma unroll
    for (int nt = 0; nt < 4; nt++) {
        *(float2*)(p1a + nt * 8) = make_float2(rna(O0[nt][0] * c0r[0]), rna(O0[nt][1] * c0r[0]));
        *(float2*)(p2a + nt * 8) = make_float2(rna(O0[nt][2] * c0r[1]), rna(O0[nt][3] * c0r[1]));
        *(float2*)(p1b + nt * 8) = make_float2(rna(O1[nt][0] * c1r[0]), rna(O1[nt][1] * c1r[0]));
        *(float2*)(p2b + nt * 8) = make_float2(rna(O1[nt][2] * c1r[1]), rna(O1[nt][3] * c1r[1]));
    }
}

// ================= 0a) weight transpose (+tf32 round) ========================
__global__ __launch_bounds__(256) void k_tr(const float* __restrict__ in,
                                            float* __restrict__ out, int R, int C) {
    __shared__ float t[32][33];
    int bx = blockIdx.x * 32, by = blockIdx.y * 32;
    int x = threadIdx.x & 31, y = threadIdx.x >> 5;
#pragma unroll
    for (int j = 0; j < 32; j += 8) t[y + j][x] = in[(size_t)(by + y + j) * C + bx + x];
    __syncthreads();
#pragma unroll
    for (int j = 0; j < 32; j += 8) out[(size_t)(bx + y + j) * R + by + x] = rna(t[x][y + j]);
}

// ================= 0b) round x to tf32 ======================================
__global__ __launch_bounds__(256) void k_rx(const float* __restrict__ x,
                                            float* __restrict__ o) {
    int i = blockIdx.x * 256 + threadIdx.x;
    float4 v = ((const float4*)x)[i];
    v.x = rna(v.x); v.y = rna(v.y); v.z = rna(v.z); v.w = rna(v.w);
    ((float4*)o)[i] = v;
}

// ================= 5) LayerNorm over C=768 ==================================
__device__ __forceinline__ float blk_reduce(float v, float* smr) {
    const unsigned full = 0xffffffffu;
#pragma unroll
    for (int o = 16; o > 0; o >>= 1) v += __shfl_xor_sync(full, v, o);
    int warp = threadIdx.x >> 5, lane = threadIdx.x & 31;
    if (lane == 0) smr[warp] = v;
    __syncthreads();
    if (warp == 0) {
        float x = (lane < 8) ? smr[lane] : 0.0f;
#pragma unroll
        for (int o = 4; o > 0; o >>= 1) x += __shfl_xor_sync(full, x, o);
        if (lane == 0) smr[0] = x;
    }
    __syncthreads();
    float r = smr[0];
    __syncthreads();
    return r;
}

__global__ __launch_bounds__(256) void k_ln(int br, const float* __restrict__ gam,
                                            const float* __restrict__ bet,
                                            float* __restrict__ out) {
    __shared__ float smr[32];
    int row = blockIdx.x;
    const float* x = g_pr[br] + (size_t)row * Cc;
    int t = threadIdx.x;
    float v[3];
#pragma unroll
    for (int i = 0; i < 3; i++) v[i] = x[t + 256 * i];
    float s = v[0] + v[1] + v[2];
    s = blk_reduce(s, smr);
    float mu = s * (1.0f / (float)Cc);
    float ss = 0.0f;
#pragma unroll
    for (int i = 0; i < 3; i++) { float d = v[i] - mu; ss += d * d; }
    ss = blk_reduce(ss, smr);
    float inv = rsqrtf(ss * (1.0f / (float)Cc) + LNEPS);
#pragma unroll
    for (int i = 0; i < 3; i++) {
        int c = t + 256 * i;
        out[(size_t)row * Cc + c] = (v[i] - mu) * inv * gam[c] + bet[c];
    }
}

// ================= launch ==================================================
extern "C" void kernel_launch(void* const* d_in, const int* in_sizes, int n_in,
                              void* d_out, int out_size) {
    const float* x    = (const float*)d_in[0];
    const float* wq0  = (const float*)d_in[1];
    const float* wq1  = (const float*)d_in[2];
    const float* wp0  = (const float*)d_in[3];
    const float* bp0  = (const float*)d_in[4];
    const float* wp1  = (const float*)d_in[5];
    const float* bp1  = (const float*)d_in[6];
    const float* temp = (const float*)d_in[7];
    const float* g0   = (const float*)d_in[8];
    const float* b0   = (const float*)d_in[9];
    const float* g1   = (const float*)d_in[10];
    const float* b1   = (const float*)d_in[11];
    float* out = (float*)d_out;

    static float* wt0 = nullptr; static float* wt1 = nullptr;
    static float* wpt0 = nullptr; static float* wpt1 = nullptr;
    static float* xr = nullptr;
    if (!wt0) {
        cudaGetSymbolAddress((void**)&wt0, g_wt);
        wt1 = wt0 + (size_t)3 * Cc * Cc;
        cudaGetSymbolAddress((void**)&wpt0, g_wpt);
        wpt1 = wpt0 + (size_t)Cc * Cc;
        cudaGetSymbolAddress((void**)&xr, g_xr);
        cudaFuncSetAttribute(k_qkv_mma, cudaFuncAttributeMaxDynamicSharedMemorySize, 65536);
        cudaFuncSetAttribute(k_proj_mma, cudaFuncAttributeMaxDynamicSharedMemorySize, 65536);
        cudaFuncSetAttribute(k_attn, cudaFuncAttributeMaxDynamicSharedMemorySize, F_SMEM);
    }

    dim3 t256(256);
    k_tr<<<dim3(72, 24), t256>>>(wq0, wt0, 768, 2304);
    k_tr<<<dim3(72, 24), t256>>>(wq1, wt1, 768, 2304);
    k_tr<<<dim3(24, 24), t256>>>(wp0, wpt0, 768, 768);
    k_tr<<<dim3(24, 24), t256>>>(wp1, wpt1, 768, 768);
    k_rx<<<dim3(6144), t256>>>(x, xr);

    k_qkv_mma<<<dim3(18, 64), t256, 65536>>>(xr, wt0, 0);
    k_qkv_mma<<<dim3(18, 64), t256, 65536>>>(xr, wt1, 1);
    k_attn<<<dim3(8, BHh), dim3(512), F_SMEM>>>(temp);
    k_proj_mma<<<dim3(6, 64), t256, 65536>>>(0, wpt0, bp0);
    k_proj_mma<<<dim3(6, 64), t256, 65536>>>(1, wpt1, bp1);
    k_ln<<<dim3(Mm), t256>>>(0, g0, b0, out);
    k_ln<<<dim3(Mm), t256>>>(1, g1, b1, out + (size_t)Mm * Cc);
}